// round 2
// baseline (speedup 1.0000x reference)
#include <cuda_runtime.h>
#include <cuda_bf16.h>
#include <cstdint>

// ---------------- problem constants ----------------
#define BATCH 256
#define LSEQ  256
#define CNODE 128
#define HID   128
#define NHEAD 4
#define DHEAD 32
#define NEDGE 4096
#define NNODE (BATCH * CNODE)       // 32768
#define OUT_ELEMS  (BATCH * LSEQ * CNODE)   // 8388608
#define ATTN_ELEMS (BATCH * CNODE * CNODE)  // 4194304

// ---------------- scratch (__device__ globals; no allocation allowed) ----------------
__device__ float g_Xt[NNODE * LSEQ];       // 32 MB  transposed x for embed GEMM
__device__ float g_h[NNODE * HID];         // 16 MB  node features
__device__ float g_xl[NNODE * HID];        // 16 MB
__device__ float g_xr[NNODE * HID];        // 16 MB
__device__ float g_om[NNODE * LSEQ];       // 32 MB  proj output before transpose
__device__ int   g_csr_ptr[CNODE + 1];
__device__ int   g_csr_src[NEDGE];

// packed f32x2 FMA (ptxas never auto-fuses; must come from PTX)
#define FMA2(d, a, b, c) \
    asm("fma.rn.f32x2 %0, %1, %2, %3;" : "=l"(d) : "l"(a), "l"(b), "l"(c))

// ---------------- CSR build: counting sort 4096 edges by dst ----------------
// edge_index may arrive as int64 (x64-enabled jax) or int32 (default jax silently
// downcasts). Detect on device: read the first NEDGE words as int64 (32 KB, in
// bounds under either dtype). True int64 data has every value in [0, CNODE);
// int32 data read as int64 fuses adjacent pairs -> huge values.
__global__ void build_csr_kernel(const void* __restrict__ eiraw) {
    __shared__ int cnt[CNODE];
    __shared__ int base[CNODE + 1];
    __shared__ int is64_s;
    const long long* e64 = (const long long*)eiraw;
    const int* e32 = (const int*)eiraw;
    int tid = threadIdx.x;

    if (tid == 0) is64_s = 1;
    if (tid < CNODE) cnt[tid] = 0;
    __syncthreads();
    int bad = 0;
    for (int i = tid; i < NEDGE; i += 256) {
        long long v = e64[i];
        if (v < 0 || v >= CNODE) bad = 1;
    }
    if (bad) is64_s = 0;      // benign race: any writer writes 0
    __syncthreads();
    const int is64 = is64_s;

    for (int e = tid; e < NEDGE; e += 256) {
        int d = is64 ? (int)e64[NEDGE + e] : e32[NEDGE + e];
        atomicAdd(&cnt[d], 1);
    }
    __syncthreads();
    if (tid == 0) {
        int run = 0;
        for (int i = 0; i < CNODE; ++i) { base[i] = run; run += cnt[i]; }
        base[CNODE] = run;
    }
    __syncthreads();
    if (tid <= CNODE) g_csr_ptr[tid] = base[tid];
    if (tid < CNODE) cnt[tid] = base[tid];
    __syncthreads();
    for (int e = tid; e < NEDGE; e += 256) {
        int d = is64 ? (int)e64[NEDGE + e] : e32[NEDGE + e];
        int s = is64 ? (int)e64[e]         : e32[e];
        int pos = atomicAdd(&cnt[d], 1);
        g_csr_src[pos] = s;
    }
}

// ---------------- transpose x: (B,L,C) -> Xt[(b*C+c)][l] ----------------
__global__ void transpose_x_kernel(const float* __restrict__ x) {
    __shared__ float tile[32][33];
    int b = blockIdx.z;
    int l0 = blockIdx.x * 32, c0 = blockIdx.y * 32;
    int tx = threadIdx.x, ty = threadIdx.y;
    const float* src = x + (size_t)b * LSEQ * CNODE;
    #pragma unroll
    for (int i = 0; i < 32; i += 8)
        tile[ty + i][tx] = src[(size_t)(l0 + ty + i) * CNODE + c0 + tx];
    __syncthreads();
    float* dst = g_Xt + (size_t)b * CNODE * LSEQ;
    #pragma unroll
    for (int i = 0; i < 32; i += 8)
        dst[(size_t)(c0 + ty + i) * LSEQ + l0 + tx] = tile[tx][ty + i];
}

// ---------------- transpose out: om[(b*C+c)][l] -> out[(b*L+l)][c] ----------------
__global__ void transpose_out_kernel(float* __restrict__ out) {
    __shared__ float tile[32][33];
    int b = blockIdx.z;
    int l0 = blockIdx.x * 32, c0 = blockIdx.y * 32;
    int tx = threadIdx.x, ty = threadIdx.y;
    const float* src = g_om + (size_t)b * CNODE * LSEQ;
    #pragma unroll
    for (int i = 0; i < 32; i += 8)
        tile[ty + i][tx] = src[(size_t)(c0 + ty + i) * LSEQ + l0 + tx];
    __syncthreads();
    float* dst = out + (size_t)b * LSEQ * CNODE;
    #pragma unroll
    for (int i = 0; i < 32; i += 8)
        dst[(size_t)(l0 + ty + i) * CNODE + c0 + tx] = tile[tx][ty + i];
}

// ---------------- generic fp32 GEMM, C = A(MxK) @ W(KxN) + bias ----------------
// tile 64(M) x 128(N), K chunked by 32, dual-k f32x2 accumulators.
// grid: (N/128, M/64), block 256.
__global__ __launch_bounds__(256) void gemm_kernel(
    const float* __restrict__ A, int lda,
    const float* __restrict__ W, int ldb,
    const float* __restrict__ bias,
    float* __restrict__ C, int ldc, int K)
{
    __shared__ __align__(16) float A_s[64 * 32];
    __shared__ __align__(16) unsigned long long B_s[16 * 128]; // pair-major
    const int tid = threadIdx.x;
    const int tx = tid & 31, ty = tid >> 5;
    const int m0 = blockIdx.y * 64;
    const int n0 = blockIdx.x * 128;

    unsigned long long acc[8][4];
    #pragma unroll
    for (int i = 0; i < 8; ++i)
        #pragma unroll
        for (int j = 0; j < 4; ++j) acc[i][j] = 0ull;

    float* B_f = (float*)B_s;
    for (int k0 = 0; k0 < K; k0 += 32) {
        #pragma unroll
        for (int i = 0; i < 8; ++i) {
            int m = i * 8 + ty;
            A_s[m * 32 + tx] = A[(size_t)(m0 + m) * lda + k0 + tx];
        }
        #pragma unroll
        for (int i = 0; i < 16; ++i) {
            int idx = tid + i * 256;
            int kk = idx >> 7;
            int nn = idx & 127;
            B_f[(kk >> 1) * 256 + nn * 2 + (kk & 1)] = W[(size_t)(k0 + kk) * ldb + n0 + nn];
        }
        __syncthreads();
        #pragma unroll
        for (int kp = 0; kp < 16; ++kp) {
            unsigned long long b2[4];
            #pragma unroll
            for (int j = 0; j < 4; ++j)
                b2[j] = B_s[kp * 128 + tx + j * 32];
            #pragma unroll
            for (int i = 0; i < 8; ++i) {
                unsigned long long a2 = *(const unsigned long long*)(A_s + (ty * 8 + i) * 32 + kp * 2);
                #pragma unroll
                for (int j = 0; j < 4; ++j)
                    FMA2(acc[i][j], a2, b2[j], acc[i][j]);
            }
        }
        __syncthreads();
    }
    #pragma unroll
    for (int i = 0; i < 8; ++i) {
        int m = m0 + ty * 8 + i;
        #pragma unroll
        for (int j = 0; j < 4; ++j) {
            int n = n0 + tx + j * 32;
            float2 p = *(float2*)&acc[i][j];
            C[(size_t)m * ldc + n] = p.x + p.y + bias[n];
        }
    }
}

// ---------------- GAT layer kernel ----------------
// one block per batch sample; xl table (128x128) cached in shared.
// 256 threads = 2 sub-groups of 128; sub handles dst nodes [sub*64, sub*64+64).
// warp within sub = head; online softmax; ELU + residual + LayerNorm fused.
// Optional attn pass (last layer): attn_map[b, dst, src] += mean_heads(alpha).
#define GAT_SMEM_BYTES (65536 + 4096 + 520 + 1024 + 64)

__global__ __launch_bounds__(256) void gat_kernel(
    float* __restrict__ h, const float* __restrict__ xl, const float* __restrict__ xr,
    const float* __restrict__ att, const float* __restrict__ gat_bias,
    const float* __restrict__ ln_g, const float* __restrict__ ln_b,
    float* __restrict__ attn_out)
{
    extern __shared__ __align__(16) char smc[];
    float* xl_s = (float*)smc;                               // 16384 f
    unsigned char* src_s = (unsigned char*)(smc + 65536);    // 4096 B
    int* ptr_s = (int*)(smc + 65536 + 4096);                 // 129 ints (520 B w/ pad)
    float* attn_s = (float*)(smc + 65536 + 4096 + 520);      // 256 f
    float* red_s = attn_s + 256;                             // 16 f

    const int b = blockIdx.x;
    const int tid = threadIdx.x;

    {   // stage xl for this batch into shared
        const float4* src4 = (const float4*)(xl + (size_t)b * CNODE * HID);
        float4* dst4 = (float4*)xl_s;
        for (int i = tid; i < CNODE * HID / 4; i += 256) dst4[i] = src4[i];
        for (int i = tid; i < NEDGE; i += 256) src_s[i] = (unsigned char)g_csr_src[i];
        for (int i = tid; i <= CNODE; i += 256) ptr_s[i] = g_csr_ptr[i];
    }
    __syncthreads();

    const int sub = tid >> 7;
    const int t = tid & 127;
    const int lane = tid & 31;
    const int head = t >> 5;
    const float a_t = att[t];
    const float bias_t = gat_bias[t];
    const float gamma_t = ln_g[t];
    const float beta_t = ln_b[t];

    for (int nb = 0; nb < 64; ++nb) {
        const int n = nb + sub * 64;
        const size_t node = (size_t)b * CNODE + n;
        const float r_t = xr[node * HID + t];
        const int e0 = ptr_s[n], e1 = ptr_s[n + 1];

        float m = -1e30f, s = 0.f, acc = 0.f;
        for (int e = e0 - 1; e < e1; ++e) {           // e0-1 == self-loop
            const int srcn = (e < e0) ? n : (int)src_s[e];
            const float v = xl_s[srcn * HID + t];
            float xv = v + r_t;
            xv = (xv > 0.f) ? xv : 0.2f * xv;         // leaky relu
            float p = xv * a_t;
            p += __shfl_xor_sync(0xffffffffu, p, 16);
            p += __shfl_xor_sync(0xffffffffu, p, 8);
            p += __shfl_xor_sync(0xffffffffu, p, 4);
            p += __shfl_xor_sync(0xffffffffu, p, 2);
            p += __shfl_xor_sync(0xffffffffu, p, 1);
            const float logit = p;                    // warp-uniform
            if (logit > m) {                          // rare: rescale
                const float c = __expf(m - logit);
                s = s * c + 1.0f;
                acc = acc * c + v;
                m = logit;
            } else {
                const float pe = __expf(logit - m);
                s += pe;
                acc += pe * v;
            }
        }
        const float gout = acc / (s + 1e-16f);
        float hn = gout + bias_t;
        hn = (hn > 0.f) ? hn : (__expf(hn) - 1.0f);   // elu
        const float hv = h[node * HID + t] + hn;      // residual

        // LayerNorm over 128 features of this sub-group
        float sum = hv, sq = hv * hv;
        #pragma unroll
        for (int o = 16; o; o >>= 1) {
            sum += __shfl_xor_sync(0xffffffffu, sum, o);
            sq  += __shfl_xor_sync(0xffffffffu, sq, o);
        }
        if (lane == 0) { red_s[sub * 8 + head] = sum; red_s[sub * 8 + 4 + head] = sq; }
        __syncthreads();
        const float tot  = red_s[sub*8+0] + red_s[sub*8+1] + red_s[sub*8+2] + red_s[sub*8+3];
        const float tot2 = red_s[sub*8+4] + red_s[sub*8+5] + red_s[sub*8+6] + red_s[sub*8+7];
        const float mu = tot * (1.0f / 128.0f);
        const float var = tot2 * (1.0f / 128.0f) - mu * mu;
        const float inv = rsqrtf(var + 1e-5f);
        h[node * HID + t] = (hv - mu) * inv * gamma_t + beta_t;
        __syncthreads();

        if (attn_out) {
            attn_s[sub * 128 + t] = 0.f;
            __syncthreads();
            for (int e = e0 - 1; e < e1; ++e) {
                const int srcn = (e < e0) ? n : (int)src_s[e];
                const float v = xl_s[srcn * HID + t];
                float xv = v + r_t;
                xv = (xv > 0.f) ? xv : 0.2f * xv;
                float p = xv * a_t;
                p += __shfl_xor_sync(0xffffffffu, p, 16);
                p += __shfl_xor_sync(0xffffffffu, p, 8);
                p += __shfl_xor_sync(0xffffffffu, p, 4);
                p += __shfl_xor_sync(0xffffffffu, p, 2);
                p += __shfl_xor_sync(0xffffffffu, p, 1);
                const float alpha = __expf(p - m) / (s + 1e-16f);
                if (lane == 0) atomicAdd(&attn_s[sub * 128 + srcn], alpha * 0.25f);
            }
            __syncthreads();
            attn_out[(size_t)b * CNODE * CNODE + (size_t)n * CNODE + t] = attn_s[sub * 128 + t];
            __syncthreads();
        }
    }
}

// ---------------- launch ----------------
extern "C" void kernel_launch(void* const* d_in, const int* in_sizes, int n_in,
                              void* d_out, int out_size) {
    const float* x        = (const float*)d_in[0];
    const void*  ei       = d_in[1];
    const float* emb_W    = (const float*)d_in[2];
    const float* emb_b    = (const float*)d_in[3];
    const float* lin_l_W  = (const float*)d_in[4];
    const float* lin_l_b  = (const float*)d_in[5];
    const float* lin_r_W  = (const float*)d_in[6];
    const float* lin_r_b  = (const float*)d_in[7];
    const float* att      = (const float*)d_in[8];
    const float* gat_bias = (const float*)d_in[9];
    const float* ln_g     = (const float*)d_in[10];
    const float* ln_b     = (const float*)d_in[11];
    const float* proj_W   = (const float*)d_in[12];
    const float* proj_b   = (const float*)d_in[13];
    float* out = (float*)d_out;

    float *Xt, *h, *xl, *xr, *om;
    cudaGetSymbolAddress((void**)&Xt, g_Xt);
    cudaGetSymbolAddress((void**)&h,  g_h);
    cudaGetSymbolAddress((void**)&xl, g_xl);
    cudaGetSymbolAddress((void**)&xr, g_xr);
    cudaGetSymbolAddress((void**)&om, g_om);

    cudaFuncSetAttribute(gat_kernel, cudaFuncAttributeMaxDynamicSharedMemorySize, GAT_SMEM_BYTES);

    build_csr_kernel<<<1, 256>>>(ei);
    transpose_x_kernel<<<dim3(LSEQ / 32, CNODE / 32, BATCH), dim3(32, 8)>>>(x);

    // embed: h = Xt(32768x256) @ emb_W(256x128) + emb_b
    gemm_kernel<<<dim3(1, NNODE / 64), 256>>>(Xt, LSEQ, emb_W, HID, emb_b, h, HID, LSEQ);

    for (int layer = 0; layer < 2; ++layer) {
        gemm_kernel<<<dim3(1, NNODE / 64), 256>>>(h, HID, lin_l_W + layer * HID * HID, HID,
                                                  lin_l_b + layer * HID, xl, HID, HID);
        gemm_kernel<<<dim3(1, NNODE / 64), 256>>>(h, HID, lin_r_W + layer * HID * HID, HID,
                                                  lin_r_b + layer * HID, xr, HID, HID);
        float* attn_ptr = (layer == 1 && out_size >= OUT_ELEMS + ATTN_ELEMS) ? out + OUT_ELEMS : nullptr;
        gat_kernel<<<BATCH, 256, GAT_SMEM_BYTES>>>(h, xl, xr,
                                                   att + layer * HID, gat_bias + layer * HID,
                                                   ln_g + layer * HID, ln_b + layer * HID, attn_ptr);
    }

    // proj: om = h(32768x128) @ proj_W(128x256) + proj_b
    gemm_kernel<<<dim3(LSEQ / 128, NNODE / 64), 256>>>(h, HID, proj_W, LSEQ, proj_b, om, LSEQ, HID);
    transpose_out_kernel<<<dim3(LSEQ / 32, CNODE / 32, BATCH), dim3(32, 8)>>>(out);
}

// round 3
// speedup vs baseline: 4.0940x; 4.0940x over previous
#include <cuda_runtime.h>
#include <cuda_bf16.h>
#include <cstdint>

// ---------------- problem constants ----------------
#define BATCH 256
#define LSEQ  256
#define CNODE 128
#define HID   128
#define NHEAD 4
#define DHEAD 32
#define NEDGE 4096
#define NSLOT (NEDGE + CNODE)               // 4224 incl. self loops
#define NNODE (BATCH * CNODE)               // 32768
#define OUT_ELEMS  (BATCH * LSEQ * CNODE)   // 8388608
#define ATTN_ELEMS (BATCH * CNODE * CNODE)  // 4194304

// ---------------- scratch (__device__ globals; no allocation allowed) ----------------
__device__ float g_Xt[NNODE * LSEQ];       // 32 MB  transposed x for embed GEMM
__device__ float g_h[NNODE * HID];         // 16 MB  node features
__device__ float g_xl[NNODE * HID];        // 16 MB
__device__ float g_xr[NNODE * HID];        // 16 MB
__device__ float g_om[NNODE * LSEQ];       // 32 MB  proj output before transpose
__device__ int   g_slot_ptr[CNODE + 1];    // slot CSR (self-loop first per dst)
__device__ int   g_slot_src[NSLOT];

// packed f32x2 FMA (ptxas never auto-fuses; must come from PTX)
#define FMA2(d, a, b, c) \
    asm("fma.rn.f32x2 %0, %1, %2, %3;" : "=l"(d) : "l"(a), "l"(b), "l"(c))

// ---------------- CSR/slot build: counting sort 4096 edges by dst ----------------
// edge_index may arrive as int64 or int32 (jax x64 off silently downcasts).
__global__ void build_csr_kernel(const void* __restrict__ eiraw) {
    __shared__ int cnt[CNODE];
    __shared__ int base[CNODE + 1];
    __shared__ int is64_s;
    const long long* e64 = (const long long*)eiraw;
    const int* e32 = (const int*)eiraw;
    int tid = threadIdx.x;

    if (tid == 0) is64_s = 1;
    if (tid < CNODE) cnt[tid] = 0;
    __syncthreads();
    int bad = 0;
    for (int i = tid; i < NEDGE; i += 256) {
        long long v = e64[i];
        if (v < 0 || v >= CNODE) bad = 1;
    }
    if (bad) is64_s = 0;
    __syncthreads();
    const int is64 = is64_s;

    for (int e = tid; e < NEDGE; e += 256) {
        int d = is64 ? (int)e64[NEDGE + e] : e32[NEDGE + e];
        atomicAdd(&cnt[d], 1);
    }
    __syncthreads();
    if (tid == 0) {
        int run = 0;
        for (int i = 0; i < CNODE; ++i) { base[i] = run; run += cnt[i]; }
        base[CNODE] = run;
    }
    __syncthreads();
    // slot layout per dst d: [base[d]+d] = self loop, then its edges
    if (tid <= CNODE) g_slot_ptr[tid] = base[tid] + tid;
    if (tid < CNODE) {
        g_slot_src[base[tid] + tid] = tid;   // self loop
        cnt[tid] = base[tid];
    }
    __syncthreads();
    for (int e = tid; e < NEDGE; e += 256) {
        int d = is64 ? (int)e64[NEDGE + e] : e32[NEDGE + e];
        int s = is64 ? (int)e64[e]         : e32[e];
        int pos = atomicAdd(&cnt[d], 1);     // csr position
        g_slot_src[pos + d + 1] = s;         // shift past d+1 self slots
    }
}

// ---------------- transpose x: (B,L,C) -> Xt[(b*C+c)][l] ----------------
__global__ void transpose_x_kernel(const float* __restrict__ x) {
    __shared__ float tile[32][33];
    int b = blockIdx.z;
    int l0 = blockIdx.x * 32, c0 = blockIdx.y * 32;
    int tx = threadIdx.x, ty = threadIdx.y;
    const float* src = x + (size_t)b * LSEQ * CNODE;
    #pragma unroll
    for (int i = 0; i < 32; i += 8)
        tile[ty + i][tx] = src[(size_t)(l0 + ty + i) * CNODE + c0 + tx];
    __syncthreads();
    float* dst = g_Xt + (size_t)b * CNODE * LSEQ;
    #pragma unroll
    for (int i = 0; i < 32; i += 8)
        dst[(size_t)(c0 + ty + i) * LSEQ + l0 + tx] = tile[tx][ty + i];
}

// ---------------- transpose out: om[(b*C+c)][l] -> out[(b*L+l)][c] ----------------
__global__ void transpose_out_kernel(float* __restrict__ out) {
    __shared__ float tile[32][33];
    int b = blockIdx.z;
    int l0 = blockIdx.x * 32, c0 = blockIdx.y * 32;
    int tx = threadIdx.x, ty = threadIdx.y;
    const float* src = g_om + (size_t)b * CNODE * LSEQ;
    #pragma unroll
    for (int i = 0; i < 32; i += 8)
        tile[ty + i][tx] = src[(size_t)(c0 + ty + i) * LSEQ + l0 + tx];
    __syncthreads();
    float* dst = out + (size_t)b * LSEQ * CNODE;
    #pragma unroll
    for (int i = 0; i < 32; i += 8)
        dst[(size_t)(l0 + ty + i) * CNODE + c0 + tx] = tile[tx][ty + i];
}

// ---------------- generic fp32 GEMM, C = A(MxK) @ W(KxN) + bias ----------------
// tile 64(M) x 128(N), K chunked by 32, dual-k f32x2 accumulators.
__global__ __launch_bounds__(256, 2) void gemm_kernel(
    const float* __restrict__ A, int lda,
    const float* __restrict__ W, int ldb,
    const float* __restrict__ bias,
    float* __restrict__ C, int ldc, int K)
{
    __shared__ __align__(16) float A_s[64 * 32];
    __shared__ __align__(16) unsigned long long B_s[16 * 128]; // pair-major
    const int tid = threadIdx.x;
    const int tx = tid & 31, ty = tid >> 5;
    const int m0 = blockIdx.y * 64;
    const int n0 = blockIdx.x * 128;

    unsigned long long acc[8][4];
    #pragma unroll
    for (int i = 0; i < 8; ++i)
        #pragma unroll
        for (int j = 0; j < 4; ++j) acc[i][j] = 0ull;

    float* B_f = (float*)B_s;
    for (int k0 = 0; k0 < K; k0 += 32) {
        #pragma unroll
        for (int i = 0; i < 8; ++i) {
            int m = i * 8 + ty;
            A_s[m * 32 + tx] = A[(size_t)(m0 + m) * lda + k0 + tx];
        }
        #pragma unroll
        for (int i = 0; i < 16; ++i) {
            int idx = tid + i * 256;
            int kk = idx >> 7;
            int nn = idx & 127;
            B_f[(kk >> 1) * 256 + nn * 2 + (kk & 1)] = W[(size_t)(k0 + kk) * ldb + n0 + nn];
        }
        __syncthreads();
        #pragma unroll
        for (int kp = 0; kp < 16; ++kp) {
            unsigned long long b2[4];
            #pragma unroll
            for (int j = 0; j < 4; ++j)
                b2[j] = B_s[kp * 128 + tx + j * 32];
            #pragma unroll
            for (int i = 0; i < 8; ++i) {
                unsigned long long a2 = *(const unsigned long long*)(A_s + (ty * 8 + i) * 32 + kp * 2);
                #pragma unroll
                for (int j = 0; j < 4; ++j)
                    FMA2(acc[i][j], a2, b2[j], acc[i][j]);
            }
        }
        __syncthreads();
    }
    #pragma unroll
    for (int i = 0; i < 8; ++i) {
        int m = m0 + ty * 8 + i;
        #pragma unroll
        for (int j = 0; j < 4; ++j) {
            int n = n0 + tx + j * 32;
            float2 p = *(float2*)&acc[i][j];
            C[(size_t)m * ldc + n] = p.x + p.y + bias[n];
        }
    }
}

// ---------------- GAT layer kernel (warp-per-dst, all warp-local) ----------------
// Block = one batch sample, 512 threads = 16 warps. Warp w handles dsts w, w+16, ...
// Lane l owns dims [4l, 4l+4), head = l>>3.
// smem (floats): xl_s[128*132] | lbuf[16 warps][128 slots][4] | attnrow[16][128]
//                | a_s[128] | then bytes: src8[4224] | ptr[129]
#define XL_F     (CNODE * 132)                 // 16896
#define LBUF_F   (16 * 128 * 4)                // 8192
#define ATTN_F   (16 * 128)                    // 2048
#define A_F      128
#define SMEM_F   (XL_F + LBUF_F + ATTN_F + A_F)
#define SRC_B_OFF (SMEM_F * 4)                 // 108... bytes
#define PTR_B_OFF (SRC_B_OFF + NSLOT)          // +4224
#define GAT_SMEM_BYTES (PTR_B_OFF + (CNODE + 1) * 4)

__global__ __launch_bounds__(512, 2) void gat_kernel(
    float* __restrict__ h, const float* __restrict__ xl, const float* __restrict__ xr,
    const float* __restrict__ att, const float* __restrict__ gat_bias,
    const float* __restrict__ ln_g, const float* __restrict__ ln_b,
    float* __restrict__ attn_out)
{
    extern __shared__ __align__(16) float sm[];
    float* xl_s   = sm;                        // row-major stride 132 floats
    float* lbuf   = sm + XL_F;
    float* attnrow= sm + XL_F + LBUF_F;
    float* a_s    = sm + XL_F + LBUF_F + ATTN_F;
    unsigned char* src8 = (unsigned char*)sm + SRC_B_OFF;
    int* ptr_s = (int*)((char*)sm + PTR_B_OFF);

    const int b = blockIdx.x;
    const int tid = threadIdx.x;
    const int w = tid >> 5;
    const int l = tid & 31;
    const int hh = l >> 3;

    // ---- stage ----
    {
        const float4* src4 = (const float4*)(xl + (size_t)b * CNODE * HID);
        for (int i = tid; i < CNODE * 32; i += 512) {
            int node = i >> 5, d4 = i & 31;
            ((float4*)xl_s)[node * 33 + d4] = src4[i];
        }
        for (int i = tid; i < NSLOT; i += 512) src8[i] = (unsigned char)g_slot_src[i];
        if (tid <= CNODE) ptr_s[tid] = g_slot_ptr[tid];
        if (tid < 128) a_s[tid] = att[tid];
    }
    __syncthreads();

    const float4 a4 = ((const float4*)a_s)[l];
    const float4 bias4 = ((const float4*)gat_bias)[l];
    const float4 g4v = ((const float4*)ln_g)[l];
    const float4 b4v = ((const float4*)ln_b)[l];
    float* mybuf = lbuf + w * 512;                 // 128 slots * 4 floats
    const float4* xls4 = (const float4*)xl_s;

    for (int d = w; d < CNODE; d += 16) {
        const int sb = ptr_s[d];
        int E1 = ptr_s[d + 1] - sb;
        if (E1 > 128) E1 = 128;                    // never in practice
        const size_t node = (size_t)b * CNODE + d;
        const float4 xr4 = ((const float4*)(xr + node * HID))[l];

        // ---- pass 1: logits + per-head max ----
        float m = -1e30f;
        #pragma unroll 2
        for (int k = 0; k < E1; ++k) {
            const int src = src8[sb + k];
            const float4 v = xls4[src * 33 + l];
            float p;
            {
                float t0 = v.x + xr4.x; t0 = fmaxf(t0, 0.2f * t0);
                float t1 = v.y + xr4.y; t1 = fmaxf(t1, 0.2f * t1);
                float t2 = v.z + xr4.z; t2 = fmaxf(t2, 0.2f * t2);
                float t3 = v.w + xr4.w; t3 = fmaxf(t3, 0.2f * t3);
                p = t0 * a4.x + t1 * a4.y + t2 * a4.z + t3 * a4.w;
            }
            p += __shfl_xor_sync(0xffffffffu, p, 4);
            p += __shfl_xor_sync(0xffffffffu, p, 2);
            p += __shfl_xor_sync(0xffffffffu, p, 1);
            if ((l & 7) == 0) mybuf[k * 4 + hh] = p;
            m = fmaxf(m, p);
        }
        __syncwarp();
        float4 m4;
        m4.x = __shfl_sync(0xffffffffu, m, 0);
        m4.y = __shfl_sync(0xffffffffu, m, 8);
        m4.z = __shfl_sync(0xffffffffu, m, 16);
        m4.w = __shfl_sync(0xffffffffu, m, 24);

        // ---- pass 2: exp + sum (lane-per-slot) ----
        float4 s4 = {0.f, 0.f, 0.f, 0.f};
        for (int k = l; k < E1; k += 32) {
            float4 f = ((float4*)mybuf)[k];
            f.x = __expf(f.x - m4.x);
            f.y = __expf(f.y - m4.y);
            f.z = __expf(f.z - m4.z);
            f.w = __expf(f.w - m4.w);
            ((float4*)mybuf)[k] = f;
            s4.x += f.x; s4.y += f.y; s4.z += f.z; s4.w += f.w;
        }
        #pragma unroll
        for (int o = 16; o; o >>= 1) {
            s4.x += __shfl_xor_sync(0xffffffffu, s4.x, o);
            s4.y += __shfl_xor_sync(0xffffffffu, s4.y, o);
            s4.z += __shfl_xor_sync(0xffffffffu, s4.z, o);
            s4.w += __shfl_xor_sync(0xffffffffu, s4.w, o);
        }
        float4 rs4;
        rs4.x = 1.0f / (s4.x + 1e-16f);
        rs4.y = 1.0f / (s4.y + 1e-16f);
        rs4.z = 1.0f / (s4.z + 1e-16f);
        rs4.w = 1.0f / (s4.w + 1e-16f);
        const float rs_m = (hh == 0) ? rs4.x : (hh == 1) ? rs4.y : (hh == 2) ? rs4.z : rs4.w;
        __syncwarp();

        // ---- pass 3: aggregate + ELU + residual + LayerNorm ----
        float4 acc = {0.f, 0.f, 0.f, 0.f};
        #pragma unroll 2
        for (int k = 0; k < E1; ++k) {
            const int src = src8[sb + k];
            const float e = mybuf[k * 4 + hh];
            const float4 v = xls4[src * 33 + l];
            acc.x += e * v.x; acc.y += e * v.y; acc.z += e * v.z; acc.w += e * v.w;
        }
        float4 gout;
        gout.x = acc.x * rs_m + bias4.x;
        gout.y = acc.y * rs_m + bias4.y;
        gout.z = acc.z * rs_m + bias4.z;
        gout.w = acc.w * rs_m + bias4.w;
        gout.x = (gout.x > 0.f) ? gout.x : (__expf(gout.x) - 1.f);
        gout.y = (gout.y > 0.f) ? gout.y : (__expf(gout.y) - 1.f);
        gout.z = (gout.z > 0.f) ? gout.z : (__expf(gout.z) - 1.f);
        gout.w = (gout.w > 0.f) ? gout.w : (__expf(gout.w) - 1.f);
        float4 hv = ((const float4*)(h + node * HID))[l];
        hv.x += gout.x; hv.y += gout.y; hv.z += gout.z; hv.w += gout.w;
        float sum = hv.x + hv.y + hv.z + hv.w;
        float sq  = hv.x*hv.x + hv.y*hv.y + hv.z*hv.z + hv.w*hv.w;
        #pragma unroll
        for (int o = 16; o; o >>= 1) {
            sum += __shfl_xor_sync(0xffffffffu, sum, o);
            sq  += __shfl_xor_sync(0xffffffffu, sq, o);
        }
        const float mu = sum * (1.0f / 128.0f);
        const float var = sq * (1.0f / 128.0f) - mu * mu;
        const float inv = rsqrtf(var + 1e-5f);
        float4 ho;
        ho.x = (hv.x - mu) * inv * g4v.x + b4v.x;
        ho.y = (hv.y - mu) * inv * g4v.y + b4v.y;
        ho.z = (hv.z - mu) * inv * g4v.z + b4v.z;
        ho.w = (hv.w - mu) * inv * g4v.w + b4v.w;
        ((float4*)(h + node * HID))[l] = ho;

        // ---- pass 4: attention map row (last layer only) ----
        if (attn_out) {
            float* row = attnrow + w * 128;
            ((float4*)row)[l] = make_float4(0.f, 0.f, 0.f, 0.f);
            __syncwarp();
            for (int k = l; k < E1; k += 32) {
                const float4 e4 = ((float4*)mybuf)[k];
                const float val = 0.25f * (e4.x * rs4.x + e4.y * rs4.y +
                                           e4.z * rs4.z + e4.w * rs4.w);
                atomicAdd(&row[src8[sb + k]], val);
            }
            __syncwarp();
            ((float4*)(attn_out + (size_t)b * CNODE * CNODE + (size_t)d * CNODE))[l] =
                ((float4*)row)[l];
            __syncwarp();
        }
    }
}

// ---------------- launch ----------------
extern "C" void kernel_launch(void* const* d_in, const int* in_sizes, int n_in,
                              void* d_out, int out_size) {
    const float* x        = (const float*)d_in[0];
    const void*  ei       = d_in[1];
    const float* emb_W    = (const float*)d_in[2];
    const float* emb_b    = (const float*)d_in[3];
    const float* lin_l_W  = (const float*)d_in[4];
    const float* lin_l_b  = (const float*)d_in[5];
    const float* lin_r_W  = (const float*)d_in[6];
    const float* lin_r_b  = (const float*)d_in[7];
    const float* att      = (const float*)d_in[8];
    const float* gat_bias = (const float*)d_in[9];
    const float* ln_g     = (const float*)d_in[10];
    const float* ln_b     = (const float*)d_in[11];
    const float* proj_W   = (const float*)d_in[12];
    const float* proj_b   = (const float*)d_in[13];
    float* out = (float*)d_out;

    float *Xt, *h, *xl, *xr, *om;
    cudaGetSymbolAddress((void**)&Xt, g_Xt);
    cudaGetSymbolAddress((void**)&h,  g_h);
    cudaGetSymbolAddress((void**)&xl, g_xl);
    cudaGetSymbolAddress((void**)&xr, g_xr);
    cudaGetSymbolAddress((void**)&om, g_om);

    cudaFuncSetAttribute(gat_kernel, cudaFuncAttributeMaxDynamicSharedMemorySize, GAT_SMEM_BYTES);

    build_csr_kernel<<<1, 256>>>(ei);
    transpose_x_kernel<<<dim3(LSEQ / 32, CNODE / 32, BATCH), dim3(32, 8)>>>(x);

    // embed: h = Xt(32768x256) @ emb_W(256x128) + emb_b
    gemm_kernel<<<dim3(1, NNODE / 64), 256>>>(Xt, LSEQ, emb_W, HID, emb_b, h, HID, LSEQ);

    for (int layer = 0; layer < 2; ++layer) {
        gemm_kernel<<<dim3(1, NNODE / 64), 256>>>(h, HID, lin_l_W + layer * HID * HID, HID,
                                                  lin_l_b + layer * HID, xl, HID, HID);
        gemm_kernel<<<dim3(1, NNODE / 64), 256>>>(h, HID, lin_r_W + layer * HID * HID, HID,
                                                  lin_r_b + layer * HID, xr, HID, HID);
        float* attn_ptr = (layer == 1 && out_size >= OUT_ELEMS + ATTN_ELEMS) ? out + OUT_ELEMS : nullptr;
        gat_kernel<<<BATCH, 512, GAT_SMEM_BYTES>>>(h, xl, xr,
                                                   att + layer * HID, gat_bias + layer * HID,
                                                   ln_g + layer * HID, ln_b + layer * HID, attn_ptr);
    }

    // proj: om = h(32768x128) @ proj_W(128x256) + proj_b
    gemm_kernel<<<dim3(LSEQ / 128, NNODE / 64), 256>>>(h, HID, proj_W, LSEQ, proj_b, om, LSEQ, HID);
    transpose_out_kernel<<<dim3(LSEQ / 32, CNODE / 32, BATCH), dim3(32, 8)>>>(out);
}